// round 10
// baseline (speedup 1.0000x reference)
#include <cuda_runtime.h>
#include <cstdint>

#define NB 64
#define NC 512
#define NHW 768
#define NT 32
#define NPROTO 4000
#define NCLASS 4001
#define NG 1536
#define TPB 256
#define SMEM_BYTES (16896*4)

typedef unsigned long long ull;

// ---------------- device scratch ----------------
__device__ float g_C[NT * NB * NC];
__device__ float g_giC[NT * NB * NG];
__device__ float g_T[4032 * NG];
__device__ float g_gh[NB * NG];
__device__ float g_h[NB * NC];
__device__ ull   g_amax[2][NB];
__device__ unsigned g_barcnt, g_barsense;

struct __align__(16) U2 { ull lo, hi; };

static __device__ __forceinline__ ull ffma2(ull a, ull b, ull c) {
    ull d;
    asm("fma.rn.f32x2 %0, %1, %2, %3;" : "=l"(d) : "l"(a), "l"(b), "l"(c));
    return d;
}
static __device__ __forceinline__ float fin(ull v) {
    float2 f = *(float2*)&v;
    return f.x + f.y;
}
static __device__ __forceinline__ ull packkey(float s, int j) {
    unsigned u = __float_as_uint(s);
    u = (u & 0x80000000u) ? ~u : (u | 0x80000000u);
    return ((ull)u << 32) | (ull)(0xFFFFFFFFu - (unsigned)j);
}
static __device__ __forceinline__ void cpa16(unsigned dst, const float* src) {
    asm volatile("cp.async.cg.shared.global [%0],[%1],16;" :: "r"(dst), "l"(src));
}
static __device__ __forceinline__ void gridbar(unsigned& phase) {
    __syncthreads();
    if (threadIdx.x == 0) {
        phase += 1;
        unsigned old;
        asm volatile("atom.release.gpu.global.add.u32 %0,[%1],%2;"
                     : "=r"(old) : "l"(&g_barcnt), "r"(1u) : "memory");
        if (old == gridDim.x - 1u) {
            g_barcnt = 0u;
            asm volatile("st.release.gpu.global.u32 [%0],%1;"
                         :: "l"(&g_barsense), "r"(phase) : "memory");
        } else {
            unsigned v;
            do {
                __nanosleep(32);
                asm volatile("ld.acquire.gpu.global.u32 %0,[%1];"
                             : "=r"(v) : "l"(&g_barsense) : "memory");
            } while (v != phase);
        }
    }
    __syncthreads();
}

// smem: X buffers at 0/4352 (64 rows * 68); W buffers at 8704/12800 (4096 each)
#define LDX(buf, kk) do { _Pragma("unroll") for (int i_=0;i_<4;++i_){                  \
    int idx=tid+i_*256; int r=idx>>4, q=idx&15;                                        \
    cpa16(sb+((buf)*4352+r*68+4*q)*4, Xb+(size_t)r*xs+(kk)+4*q); } } while(0)
#define LDXP(buf, kk) do { _Pragma("unroll") for (int i_=0;i_<4;++i_){                 \
    int idx=tid+i_*256; int r=idx>>4, q=idx&15;                                        \
    cpa16(sb+((buf)*4352+r*68+4*q)*4, prow[r]+(kk)+4*q); } } while(0)
#define LDW64(buf, kk) do { _Pragma("unroll") for (int i_=0;i_<4;++i_){                \
    int idx=tid+i_*256; int r=idx>>4, q=idx&15; int row=j0+r; if(row>maxr)row=maxr;    \
    cpa16(sb+(8704+(buf)*4096+(r&1)*2048+(q*32+(r>>1))*4)*4,                           \
          Wb+(size_t)row*ws+(kk)+4*q); } } while(0)
#define LDW32(buf, kk) do { _Pragma("unroll") for (int i_=0;i_<2;++i_){                \
    int idx=tid+i_*256; int r=idx>>4, q=idx&15;                                        \
    cpa16(sb+(8704+(buf)*4096+(q*32+r)*4)*4, Wb+(size_t)r*ws+(kk)+4*q); } } while(0)
#define LDW16(buf, kk) do { int r=tid>>4, q=tid&15;                                    \
    cpa16(sb+(8704+(buf)*4096+(q*16+r)*4)*4, Wb+(size_t)r*ws+(kk)+4*q); } while(0)
#define COMMIT() asm volatile("cp.async.commit_group;")
#define WAIT1()  asm volatile("cp.async.wait_group 1;")
#define WAIT0()  asm volatile("cp.async.wait_group 0;")

static __device__ __forceinline__ void core64(ull acc[8][2], const float* Xs,
                                              const U2* We, const U2* Wo,
                                              int lane, int b0) {
#pragma unroll 4
    for (int q = 0; q < 16; ++q) {
        U2 we = We[q * 32 + lane];
        U2 wo = Wo[q * 32 + lane];
#pragma unroll
        for (int r = 0; r < 8; ++r) {
            U2 xv = *(const U2*)(Xs + (b0 + r) * 68 + 4 * q);
            acc[r][0] = ffma2(xv.lo, we.lo, acc[r][0]);
            acc[r][0] = ffma2(xv.hi, we.hi, acc[r][0]);
            acc[r][1] = ffma2(xv.lo, wo.lo, acc[r][1]);
            acc[r][1] = ffma2(xv.hi, wo.hi, acc[r][1]);
        }
    }
}

// 64x64 unit, 8 K-chunks (used in phase 0b)
static __device__ void gemm64(ull acc[8][2], const float* Xb, size_t xs,
                              const float* const* prow, const float* Wb, size_t ws,
                              int j0, int maxr, int tid, unsigned sb, float* S) {
    const int lane = tid & 31, b0 = (tid >> 5) << 3;
#pragma unroll
    for (int r = 0; r < 8; ++r) { acc[r][0] = 0ull; acc[r][1] = 0ull; }
    if (prow) LDXP(0, 0); else LDX(0, 0);
    LDW64(0, 0); COMMIT();
    for (int c = 0; c < 8; ++c) {
        int buf = c & 1;
        if (c < 7) {
            int k = (c + 1) * 64;
            if (prow) LDXP(buf ^ 1, k); else LDX(buf ^ 1, k);
            LDW64(buf ^ 1, k); COMMIT(); WAIT1();
        } else WAIT0();
        __syncthreads();
        const U2* We = (const U2*)(S + 8704 + buf * 4096);
        core64(acc, S + buf * 4352, We, We + 512, lane, b0);
        __syncthreads();
    }
}

extern __shared__ float S[];

__global__ __launch_bounds__(TPB, 2)
void mega(const float* __restrict__ feat, const float* __restrict__ A,
          const float* __restrict__ protos, const float* __restrict__ semb,
          const float* __restrict__ sta, const float* __restrict__ unkv,
          const float* __restrict__ Wih, const float* __restrict__ Whh,
          const float* __restrict__ bih, const float* __restrict__ bhh,
          const float* __restrict__ alphap, const float* __restrict__ biasp,
          const float* __restrict__ unkscrp, float* __restrict__ out) {
    __shared__ const float* prow[64];
    const int tid = threadIdx.x, bid = blockIdx.x;
    const int grid = gridDim.x;
    const int gid = bid * TPB + tid, gth = grid * TPB;
    const int lane = tid & 31, b0 = (tid >> 5) << 3;
    unsigned sb = (unsigned)__cvta_generic_to_shared(S);
    unsigned phase = *(volatile unsigned*)&g_barsense;
    const float alpha = *alphap, bias = *biasp, unkscr = *unkscrp;

    // -------- P0a: init + out_attns + einsum --------
    for (int i = gid; i < NB * NC; i += gth) g_h[i] = 0.f;
    if (gid < NB) {
        g_amax[1][gid] = (ull)(0xFFFFFFFFu - 4001u);  // sentinel -> STA row
        g_amax[0][gid] = 0ull;
    }
    {
        const float4* A4 = (const float4*)A;
        float4* O4 = (float4*)(out + (size_t)NB * NT * NCLASS);
        for (int i = gid; i < NB * NT * NHW / 4; i += gth) O4[i] = A4[i];
    }
    for (int u = bid; u < 512; u += grid) {  // einsum: 64 c-rows x 32 t-cols, K=768
        const int b = u & 63, c0 = (u >> 6) << 6;
        const float* Xb = feat + ((size_t)b * NC + c0) * NHW; size_t xs = NHW;
        const float* Wb = A + (size_t)b * NT * NHW; size_t ws = NHW;
        ull acc[8];
#pragma unroll
        for (int r = 0; r < 8; ++r) acc[r] = 0ull;
        LDX(0, 0); LDW32(0, 0); COMMIT();
        for (int c = 0; c < 12; ++c) {
            int buf = c & 1;
            if (c < 11) { LDX(buf ^ 1, (c + 1) * 64); LDW32(buf ^ 1, (c + 1) * 64); COMMIT(); WAIT1(); }
            else WAIT0();
            __syncthreads();
            const float* Xs = S + buf * 4352;
            const U2* Wq = (const U2*)(S + 8704 + buf * 4096);
#pragma unroll 4
            for (int q = 0; q < 16; ++q) {
                U2 wq = Wq[q * 32 + lane];
#pragma unroll
                for (int r = 0; r < 8; ++r) {
                    U2 xv = *(const U2*)(Xs + (b0 + r) * 68 + 4 * q);
                    acc[r] = ffma2(xv.lo, wq.lo, acc[r]);
                    acc[r] = ffma2(xv.hi, wq.hi, acc[r]);
                }
            }
            __syncthreads();
        }
#pragma unroll
        for (int r = 0; r < 8; ++r)
            g_C[(size_t)lane * NB * NC + (size_t)b * NC + c0 + b0 + r] = fin(acc[r]);
        __syncthreads();
    }
    gridbar(phase);

    // -------- P0b: giC (768 units) + T table (1512 units), 64x64 K=512 --------
    for (int u = bid; u < 2280; u += grid) {
        ull acc[8][2];
        if (u < 768) {
            const int m0 = (u & 31) << 6, j0 = (u >> 5) << 6;
            gemm64(acc, g_C + (size_t)m0 * NC, NC, 0, Wih, 1024, j0, NG - 1, tid, sb, S);
#pragma unroll
            for (int r = 0; r < 8; ++r)
                *(float2*)&g_giC[(size_t)(m0 + b0 + r) * NG + j0 + 2 * lane] =
                    make_float2(fin(acc[r][0]), fin(acc[r][1]));
        } else {
            const int u3 = u - 768;
            const int r0 = (u3 % 63) << 6, j0 = (u3 / 63) << 6;
            if (tid < 64) {
                int i = r0 + tid; if (i > NPROTO + 1) i = NPROTO + 1;
                prow[tid] = (i < NPROTO) ? semb + (size_t)i * NC : ((i == NPROTO) ? unkv : sta);
            }
            __syncthreads();
            gemm64(acc, 0, 0, prow, Wih + 512, 1024, j0, NG - 1, tid, sb, S);
#pragma unroll
            for (int r = 0; r < 8; ++r)
                *(float2*)&g_T[(size_t)(r0 + b0 + r) * NG + j0 + 2 * lane] =
                    make_float2(fin(acc[r][0]), fin(acc[r][1]));
        }
    }
    gridbar(phase);

    // -------- time loop: 2 barriers/step --------
    for (int t = 0; t <= NT; ++t) {
        const int rawC = (t >= 1) ? 250 : 0;        // raw(t-1): 64b x 16j, K=512
        const int ghC = (t < NT) ? 48 : 0;          // gh(t):   64b x 32j, K=512
        const int tp = t - 1;
        // ---- phase A: full-K GEMMs; raw writes scores + argmax directly ----
        for (int u = bid; u < rawC + ghC; u += grid) {
            const float* Xb = g_h; size_t xs = NC, ws = NC;
            if (u < rawC) {
                const int j0 = u << 4;
                const float* Wb = protos + (size_t)j0 * NC;
                const int col = tid & 15, tr = tid >> 4;   // rows 4tr..4tr+3
                ull acc[4] = {};
                LDX(0, 0); LDW16(0, 0); COMMIT();
                for (int c = 0; c < 8; ++c) {
                    int buf = c & 1;
                    if (c < 7) { LDX(buf ^ 1, (c + 1) * 64); LDW16(buf ^ 1, (c + 1) * 64); COMMIT(); WAIT1(); }
                    else WAIT0();
                    __syncthreads();
                    const float* Xs = S + buf * 4352;
                    const U2* Wq = (const U2*)(S + 8704 + buf * 4096);
#pragma unroll 4
                    for (int q = 0; q < 16; ++q) {
                        U2 wv = Wq[q * 16 + col];
#pragma unroll
                        for (int i = 0; i < 4; ++i) {
                            U2 xv = *(const U2*)(Xs + (4 * tr + i) * 68 + 4 * q);
                            acc[i] = ffma2(xv.lo, wv.lo, acc[i]);
                            acc[i] = ffma2(xv.hi, wv.hi, acc[i]);
                        }
                    }
                    __syncthreads();
                }
                ull key[4];
#pragma unroll
                for (int i = 0; i < 4; ++i) {
                    int b = 4 * tr + i;
                    float sc = fin(acc[i]) * alpha + bias;
                    out[((size_t)b * NT + tp) * NCLASS + j0 + col] = sc;
                    key[i] = packkey(sc, j0 + col);
                }
#pragma unroll
                for (int off = 8; off >= 1; off >>= 1)
#pragma unroll
                    for (int i = 0; i < 4; ++i) {
                        ull o = __shfl_xor_sync(0xFFFFFFFFu, key[i], off);
                        if (o > key[i]) key[i] = o;
                    }
                if (col == 0)
#pragma unroll
                    for (int i = 0; i < 4; ++i)
                        atomicMax(&g_amax[tp & 1][4 * tr + i], key[i]);
            } else {
                const int j0 = (u - rawC) << 5;
                const float* Wb = Whh + (size_t)j0 * NC;
                const int wr = tid >> 5;                    // rows 8wr..8wr+7
                ull acc[8] = {};
                LDX(0, 0); LDW32(0, 0); COMMIT();
                for (int c = 0; c < 8; ++c) {
                    int buf = c & 1;
                    if (c < 7) { LDX(buf ^ 1, (c + 1) * 64); LDW32(buf ^ 1, (c + 1) * 64); COMMIT(); WAIT1(); }
                    else WAIT0();
                    __syncthreads();
                    const float* Xs = S + buf * 4352;
                    const U2* Wq = (const U2*)(S + 8704 + buf * 4096);
#pragma unroll 4
                    for (int q = 0; q < 16; ++q) {
                        U2 wv = Wq[q * 32 + lane];
#pragma unroll
                        for (int i = 0; i < 8; ++i) {
                            U2 xv = *(const U2*)(Xs + (8 * wr + i) * 68 + 4 * q);
                            acc[i] = ffma2(xv.lo, wv.lo, acc[i]);
                            acc[i] = ffma2(xv.hi, wv.hi, acc[i]);
                        }
                    }
                    __syncthreads();
                }
#pragma unroll
                for (int i = 0; i < 8; ++i)
                    g_gh[(8 * wr + i) * NG + j0 + lane] = fin(acc[i]);
            }
        }
        if (t >= 1 && bid == grid - 1 && tid < NB) {  // UNK column
            out[((size_t)tid * NT + tp) * NCLASS + NPROTO] = unkscr;
            atomicMax(&g_amax[tp & 1][tid], packkey(unkscr, NPROTO));
        }
        gridbar(phase);

        // ---- phase C: GRU pointwise + reset next argmax slot ----
        if (t < NT) {
            if (gid < NB * NC) {
                const int b = gid >> 9, c = gid & 511;
                unsigned idx = 0xFFFFFFFFu - (unsigned)(g_amax[(t + 1) & 1][b] & 0xFFFFFFFFull);
                const float* Tr = g_T + (size_t)idx * NG;
                const float* Gi = g_giC + ((size_t)t * NB + b) * NG;
                const float* Gh = g_gh + (size_t)b * NG;
                float ir = Gi[c] + Tr[c] + bih[c];
                float iz = Gi[512 + c] + Tr[512 + c] + bih[512 + c];
                float inn = Gi[1024 + c] + Tr[1024 + c] + bih[1024 + c];
                float hr = Gh[c] + bhh[c];
                float hz = Gh[512 + c] + bhh[512 + c];
                float hn = Gh[1024 + c] + bhh[1024 + c];
                double r = 1.0 / (1.0 + exp(-(double)(ir + hr)));
                double z = 1.0 / (1.0 + exp(-(double)(iz + hz)));
                double n = tanh((double)inn + r * (double)hn);
                float hold = g_h[gid];
                g_h[gid] = (float)((1.0 - z) * n + z * (double)hold);
            }
            if (bid == 0 && tid < NB) g_amax[t & 1][tid] = 0ull;  // slot for argmax(t)
        }
        gridbar(phase);
    }
}

extern "C" void kernel_launch(void* const* d_in, const int* in_sizes, int n_in,
                              void* d_out, int out_size) {
    const float* feature = (const float*)d_in[0];
    const float* A       = (const float*)d_in[1];
    const float* protos  = (const float*)d_in[2];
    const float* semb    = (const float*)d_in[3];
    const float* sta     = (const float*)d_in[4];
    const float* unkv    = (const float*)d_in[5];
    const float* Wih     = (const float*)d_in[6];
    const float* Whh     = (const float*)d_in[7];
    const float* bih     = (const float*)d_in[8];
    const float* bhh     = (const float*)d_in[9];
    const float* alphap  = (const float*)d_in[10];
    const float* biasp   = (const float*)d_in[11];
    const float* unkscrp = (const float*)d_in[12];
    float* out = (float*)d_out;

    int dev = 0; cudaGetDevice(&dev);
    int sms = 148;
    cudaDeviceGetAttribute(&sms, cudaDevAttrMultiProcessorCount, dev);
    cudaFuncSetAttribute(mega, cudaFuncAttributeMaxDynamicSharedMemorySize, SMEM_BYTES);
    mega<<<2 * sms, TPB, SMEM_BYTES>>>(feature, A, protos, semb, sta, unkv,
                                       Wih, Whh, bih, bhh, alphap, biasp, unkscrp, out);
}

// round 11
// speedup vs baseline: 1.0198x; 1.0198x over previous
#include <cuda_runtime.h>
#include <cstdint>

#define NB 64
#define NC 512
#define NHW 768
#define NT 32
#define NPROTO 4000
#define NCLASS 4001
#define NG 1536
#define TPB 256
#define SMEM_BYTES (16896*4)

typedef unsigned long long ull;

// ---------------- device scratch ----------------
__device__ float g_C[NT * NB * NC];
__device__ float g_giC[NT * NB * NG];
__device__ float g_T[4032 * NG];
__device__ float g_gh[NB * NG];
__device__ float g_h[NB * NC];
__device__ ull   g_amax[2][NB];
__device__ unsigned g_gcnt[64];          // two-level barrier: group counters
__device__ unsigned g_barcnt, g_barsense;

struct __align__(16) U2 { ull lo, hi; };

static __device__ __forceinline__ ull ffma2(ull a, ull b, ull c) {
    ull d;
    asm("fma.rn.f32x2 %0, %1, %2, %3;" : "=l"(d) : "l"(a), "l"(b), "l"(c));
    return d;
}
static __device__ __forceinline__ float fin(ull v) {
    float2 f = *(float2*)&v;
    return f.x + f.y;
}
static __device__ __forceinline__ ull packkey(float s, int j) {
    unsigned u = __float_as_uint(s);
    u = (u & 0x80000000u) ? ~u : (u | 0x80000000u);
    return ((ull)u << 32) | (ull)(0xFFFFFFFFu - (unsigned)j);
}
static __device__ __forceinline__ void cpa16(unsigned dst, const float* src) {
    asm volatile("cp.async.cg.shared.global [%0],[%1],16;" :: "r"(dst), "l"(src));
}

// two-level grid barrier: 8-block groups -> global counter -> sense
static __device__ __forceinline__ void gridbar(unsigned& phase) {
    __syncthreads();
    if (threadIdx.x == 0) {
        phase += 1;
        const unsigned grid = gridDim.x;
        const unsigned g = blockIdx.x >> 3;
        const unsigned ngroups = (grid + 7u) >> 3;
        unsigned gsz = grid - (g << 3); if (gsz > 8u) gsz = 8u;
        unsigned old;
        asm volatile("atom.acq_rel.gpu.global.add.u32 %0,[%1],%2;"
                     : "=r"(old) : "l"(&g_gcnt[g]), "r"(1u) : "memory");
        if (old == gsz - 1u) {
            g_gcnt[g] = 0u;
            unsigned old2;
            asm volatile("atom.acq_rel.gpu.global.add.u32 %0,[%1],%2;"
                         : "=r"(old2) : "l"(&g_barcnt), "r"(1u) : "memory");
            if (old2 == ngroups - 1u) {
                g_barcnt = 0u;
                asm volatile("st.release.gpu.global.u32 [%0],%1;"
                             :: "l"(&g_barsense), "r"(phase) : "memory");
            }
        }
        unsigned v;
        do {
            asm volatile("ld.acquire.gpu.global.u32 %0,[%1];"
                         : "=r"(v) : "l"(&g_barsense) : "memory");
            if (v == phase) break;
            __nanosleep(32);
        } while (1);
    }
    __syncthreads();
}

// smem: X buffers at 0/4352 (64 rows * 68); W buffers at 8704/12800 (4096 each)
#define LDX(buf, kk) do { _Pragma("unroll") for (int i_=0;i_<4;++i_){                  \
    int idx=tid+i_*256; int r=idx>>4, q=idx&15;                                        \
    cpa16(sb+((buf)*4352+r*68+4*q)*4, Xb+(size_t)r*xs+(kk)+4*q); } } while(0)
#define LDXP(buf, kk) do { _Pragma("unroll") for (int i_=0;i_<4;++i_){                 \
    int idx=tid+i_*256; int r=idx>>4, q=idx&15;                                        \
    cpa16(sb+((buf)*4352+r*68+4*q)*4, prow[r]+(kk)+4*q); } } while(0)
#define LDW64(buf, kk) do { _Pragma("unroll") for (int i_=0;i_<4;++i_){                \
    int idx=tid+i_*256; int r=idx>>4, q=idx&15; int row=j0+r; if(row>maxr)row=maxr;    \
    cpa16(sb+(8704+(buf)*4096+(r&1)*2048+(q*32+(r>>1))*4)*4,                           \
          Wb+(size_t)row*ws+(kk)+4*q); } } while(0)
#define LDW32(buf, kk) do { _Pragma("unroll") for (int i_=0;i_<2;++i_){                \
    int idx=tid+i_*256; int r=idx>>4, q=idx&15;                                        \
    cpa16(sb+(8704+(buf)*4096+(q*32+r)*4)*4, Wb+(size_t)r*ws+(kk)+4*q); } } while(0)
#define COMMIT() asm volatile("cp.async.commit_group;")
#define WAIT1()  asm volatile("cp.async.wait_group 1;")
#define WAIT0()  asm volatile("cp.async.wait_group 0;")

static __device__ __forceinline__ void core64(ull acc[8][2], const float* Xs,
                                              const U2* We, const U2* Wo,
                                              int lane, int b0) {
#pragma unroll 4
    for (int q = 0; q < 16; ++q) {
        U2 we = We[q * 32 + lane];
        U2 wo = Wo[q * 32 + lane];
#pragma unroll
        for (int r = 0; r < 8; ++r) {
            U2 xv = *(const U2*)(Xs + (b0 + r) * 68 + 4 * q);
            acc[r][0] = ffma2(xv.lo, we.lo, acc[r][0]);
            acc[r][0] = ffma2(xv.hi, we.hi, acc[r][0]);
            acc[r][1] = ffma2(xv.lo, wo.lo, acc[r][1]);
            acc[r][1] = ffma2(xv.hi, wo.hi, acc[r][1]);
        }
    }
}

// 64x64 unit, 8 K-chunks (phase 0b)
static __device__ void gemm64(ull acc[8][2], const float* Xb, size_t xs,
                              const float* const* prow, const float* Wb, size_t ws,
                              int j0, int maxr, int tid, unsigned sb, float* S) {
    const int lane = tid & 31, b0 = (tid >> 5) << 3;
#pragma unroll
    for (int r = 0; r < 8; ++r) { acc[r][0] = 0ull; acc[r][1] = 0ull; }
    if (prow) LDXP(0, 0); else LDX(0, 0);
    LDW64(0, 0); COMMIT();
    for (int c = 0; c < 8; ++c) {
        int buf = c & 1;
        if (c < 7) {
            int k = (c + 1) * 64;
            if (prow) LDXP(buf ^ 1, k); else LDX(buf ^ 1, k);
            LDW64(buf ^ 1, k); COMMIT(); WAIT1();
        } else WAIT0();
        __syncthreads();
        const U2* We = (const U2*)(S + 8704 + buf * 4096);
        core64(acc, S + buf * 4352, We, We + 512, lane, b0);
        __syncthreads();
    }
}

// 64x32 unit, K=512 (step GEMMs): rows 8wr..8wr+7, col = j0+lane
static __device__ void gemm32(ull acc[8], const float* Xb, const float* Wb,
                              int tid, unsigned sb, float* S) {
    const int lane = tid & 31, wr = tid >> 5;
    size_t xs = NC, ws = NC;
#pragma unroll
    for (int r = 0; r < 8; ++r) acc[r] = 0ull;
    LDX(0, 0); LDW32(0, 0); COMMIT();
    for (int c = 0; c < 8; ++c) {
        int buf = c & 1;
        if (c < 7) { LDX(buf ^ 1, (c + 1) * 64); LDW32(buf ^ 1, (c + 1) * 64); COMMIT(); WAIT1(); }
        else WAIT0();
        __syncthreads();
        const float* Xs = S + buf * 4352;
        const U2* Wq = (const U2*)(S + 8704 + buf * 4096);
#pragma unroll 4
        for (int q = 0; q < 16; ++q) {
            U2 wv = Wq[q * 32 + lane];
#pragma unroll
            for (int i = 0; i < 8; ++i) {
                U2 xv = *(const U2*)(Xs + (8 * wr + i) * 68 + 4 * q);
                acc[i] = ffma2(xv.lo, wv.lo, acc[i]);
                acc[i] = ffma2(xv.hi, wv.hi, acc[i]);
            }
        }
        __syncthreads();
    }
}

extern __shared__ float S[];

__global__ __launch_bounds__(TPB, 2)
void mega(const float* __restrict__ feat, const float* __restrict__ A,
          const float* __restrict__ protos, const float* __restrict__ semb,
          const float* __restrict__ sta, const float* __restrict__ unkv,
          const float* __restrict__ Wih, const float* __restrict__ Whh,
          const float* __restrict__ bih, const float* __restrict__ bhh,
          const float* __restrict__ alphap, const float* __restrict__ biasp,
          const float* __restrict__ unkscrp, float* __restrict__ out) {
    __shared__ const float* prow[64];
    const int tid = threadIdx.x, bid = blockIdx.x;
    const int grid = gridDim.x;
    const int gid = bid * TPB + tid, gth = grid * TPB;
    const int lane = tid & 31, b0 = (tid >> 5) << 3;
    unsigned sb = (unsigned)__cvta_generic_to_shared(S);
    unsigned phase = *(volatile unsigned*)&g_barsense;
    const float alpha = *alphap, bias = *biasp, unkscr = *unkscrp;

    // -------- P0a: init + out_attns + einsum --------
    for (int i = gid; i < NB * NC; i += gth) g_h[i] = 0.f;
    if (gid < NB) {
        g_amax[1][gid] = (ull)(0xFFFFFFFFu - 4001u);  // sentinel -> STA row
        g_amax[0][gid] = 0ull;
    }
    {
        const float4* A4 = (const float4*)A;
        float4* O4 = (float4*)(out + (size_t)NB * NT * NCLASS);
        for (int i = gid; i < NB * NT * NHW / 4; i += gth) O4[i] = A4[i];
    }
    for (int u = bid; u < 512; u += grid) {  // einsum: 64 c-rows x 32 t-cols, K=768
        const int b = u & 63, c0 = (u >> 6) << 6;
        const float* Xb = feat + ((size_t)b * NC + c0) * NHW; size_t xs = NHW;
        const float* Wb = A + (size_t)b * NT * NHW; size_t ws = NHW;
        ull acc[8];
#pragma unroll
        for (int r = 0; r < 8; ++r) acc[r] = 0ull;
        LDX(0, 0); LDW32(0, 0); COMMIT();
        for (int c = 0; c < 12; ++c) {
            int buf = c & 1;
            if (c < 11) { LDX(buf ^ 1, (c + 1) * 64); LDW32(buf ^ 1, (c + 1) * 64); COMMIT(); WAIT1(); }
            else WAIT0();
            __syncthreads();
            const float* Xs = S + buf * 4352;
            const U2* Wq = (const U2*)(S + 8704 + buf * 4096);
#pragma unroll 4
            for (int q = 0; q < 16; ++q) {
                U2 wq = Wq[q * 32 + lane];
#pragma unroll
                for (int r = 0; r < 8; ++r) {
                    U2 xv = *(const U2*)(Xs + (b0 + r) * 68 + 4 * q);
                    acc[r] = ffma2(xv.lo, wq.lo, acc[r]);
                    acc[r] = ffma2(xv.hi, wq.hi, acc[r]);
                }
            }
            __syncthreads();
        }
#pragma unroll
        for (int r = 0; r < 8; ++r)
            g_C[(size_t)lane * NB * NC + (size_t)b * NC + c0 + b0 + r] = fin(acc[r]);
        __syncthreads();
    }
    gridbar(phase);

    // -------- P0b: giC (768 units) + T table (1512 units), 64x64 K=512 --------
    for (int u = bid; u < 2280; u += grid) {
        ull acc[8][2];
        if (u < 768) {
            const int m0 = (u & 31) << 6, j0 = (u >> 5) << 6;
            gemm64(acc, g_C + (size_t)m0 * NC, NC, 0, Wih, 1024, j0, NG - 1, tid, sb, S);
#pragma unroll
            for (int r = 0; r < 8; ++r)
                *(float2*)&g_giC[(size_t)(m0 + b0 + r) * NG + j0 + 2 * lane] =
                    make_float2(fin(acc[r][0]), fin(acc[r][1]));
        } else {
            const int u3 = u - 768;
            const int r0 = (u3 % 63) << 6, j0 = (u3 / 63) << 6;
            if (tid < 64) {
                int i = r0 + tid; if (i > NPROTO + 1) i = NPROTO + 1;
                prow[tid] = (i < NPROTO) ? semb + (size_t)i * NC : ((i == NPROTO) ? unkv : sta);
            }
            __syncthreads();
            gemm64(acc, 0, 0, prow, Wih + 512, 1024, j0, NG - 1, tid, sb, S);
#pragma unroll
            for (int r = 0; r < 8; ++r)
                *(float2*)&g_T[(size_t)(r0 + b0 + r) * NG + j0 + 2 * lane] =
                    make_float2(fin(acc[r][0]), fin(acc[r][1]));
        }
    }
    gridbar(phase);

    // -------- time loop: 2 barriers/step, 173 identical balanced units --------
    for (int t = 0; t <= NT; ++t) {
        const int rawC = (t >= 1) ? 125 : 0;        // raw(t-1): 64b x 32j, K=512
        const int ghC = (t < NT) ? 48 : 0;          // gh(t):   64b x 32j, K=512
        const int tp = t - 1;
        // ---- phase A: full-K GEMMs; raw fuses score write + argmax ----
        for (int u = bid; u < rawC + ghC; u += grid) {
            ull acc[8];
            const int wr = tid >> 5;
            if (u < rawC) {
                const int j0 = u << 5;
                gemm32(acc, g_h, protos + (size_t)j0 * NC, tid, sb, S);
                ull key[8];
#pragma unroll
                for (int i = 0; i < 8; ++i) {
                    int b = 8 * wr + i;
                    float sc = fin(acc[i]) * alpha + bias;
                    out[((size_t)b * NT + tp) * NCLASS + j0 + lane] = sc;
                    key[i] = packkey(sc, j0 + lane);
                }
#pragma unroll
                for (int off = 16; off >= 1; off >>= 1)
#pragma unroll
                    for (int i = 0; i < 8; ++i) {
                        ull o = __shfl_xor_sync(0xFFFFFFFFu, key[i], off);
                        if (o > key[i]) key[i] = o;
                    }
                if (lane == 0)
#pragma unroll
                    for (int i = 0; i < 8; ++i)
                        atomicMax(&g_amax[tp & 1][8 * wr + i], key[i]);
            } else {
                const int j0 = (u - rawC) << 5;
                gemm32(acc, g_h, Whh + (size_t)j0 * NC, tid, sb, S);
#pragma unroll
                for (int i = 0; i < 8; ++i)
                    g_gh[(8 * wr + i) * NG + j0 + lane] = fin(acc[i]);
            }
        }
        if (t >= 1 && bid == grid - 1 && tid < NB) {  // UNK column
            out[((size_t)tid * NT + tp) * NCLASS + NPROTO] = unkscr;
            atomicMax(&g_amax[tp & 1][tid], packkey(unkscr, NPROTO));
        }
        gridbar(phase);

        // ---- phase C: GRU pointwise + reset next argmax slot ----
        if (t < NT) {
            if (gid < NB * NC) {
                const int b = gid >> 9, c = gid & 511;
                unsigned idx = 0xFFFFFFFFu - (unsigned)(g_amax[(t + 1) & 1][b] & 0xFFFFFFFFull);
                const float* Tr = g_T + (size_t)idx * NG;
                const float* Gi = g_giC + ((size_t)t * NB + b) * NG;
                const float* Gh = g_gh + (size_t)b * NG;
                float ir = Gi[c] + Tr[c] + bih[c];
                float iz = Gi[512 + c] + Tr[512 + c] + bih[512 + c];
                float inn = Gi[1024 + c] + Tr[1024 + c] + bih[1024 + c];
                float hr = Gh[c] + bhh[c];
                float hz = Gh[512 + c] + bhh[512 + c];
                float hn = Gh[1024 + c] + bhh[1024 + c];
                double r = 1.0 / (1.0 + exp(-(double)(ir + hr)));
                double z = 1.0 / (1.0 + exp(-(double)(iz + hz)));
                double n = tanh((double)inn + r * (double)hn);
                float hold = g_h[gid];
                g_h[gid] = (float)((1.0 - z) * n + z * (double)hold);
            }
            if (bid == 0 && tid < NB) g_amax[t & 1][tid] = 0ull;  // slot for argmax(t)
        }
        gridbar(phase);
    }
}

extern "C" void kernel_launch(void* const* d_in, const int* in_sizes, int n_in,
                              void* d_out, int out_size) {
    const float* feature = (const float*)d_in[0];
    const float* A       = (const float*)d_in[1];
    const float* protos  = (const float*)d_in[2];
    const float* semb    = (const float*)d_in[3];
    const float* sta     = (const float*)d_in[4];
    const float* unkv    = (const float*)d_in[5];
    const float* Wih     = (const float*)d_in[6];
    const float* Whh     = (const float*)d_in[7];
    const float* bih     = (const float*)d_in[8];
    const float* bhh     = (const float*)d_in[9];
    const float* alphap  = (const float*)d_in[10];
    const float* biasp   = (const float*)d_in[11];
    const float* unkscrp = (const float*)d_in[12];
    float* out = (float*)d_out;

    int dev = 0; cudaGetDevice(&dev);
    int sms = 148;
    cudaDeviceGetAttribute(&sms, cudaDevAttrMultiProcessorCount, dev);
    cudaFuncSetAttribute(mega, cudaFuncAttributeMaxDynamicSharedMemorySize, SMEM_BYTES);
    mega<<<2 * sms, TPB, SMEM_BYTES>>>(feature, A, protos, semb, sta, unkv,
                                       Wih, Whh, bih, bhh, alphap, biasp, unkscrp, out);
}

// round 14
// speedup vs baseline: 1.2187x; 1.1951x over previous
#include <cuda_runtime.h>
#include <cstdint>

#define NB 64
#define NC 512
#define NHW 768
#define NT 32
#define NPROTO 4000
#define NCLASS 4001
#define NG 1536
#define TPB 256
#define NSL 4
#define SMEM_BYTES (16896*4)

typedef unsigned long long ull;

// ---------------- device scratch ----------------
__device__ float g_C[NT * NB * NC];
__device__ float g_giC[NT * NB * NG];
__device__ float g_T[4032 * NG];
__device__ float g_Praw[NSL * NB * 4032];
__device__ float g_Pgh[NSL * NB * NG];
__device__ float g_h[NB * NC];
__device__ ull   g_amax[2][NB];
__device__ unsigned g_tick;
__device__ unsigned g_gcnt[64];
__device__ unsigned g_barcnt, g_barsense;

struct __align__(16) U2 { ull lo, hi; };

static __device__ __forceinline__ ull ffma2(ull a, ull b, ull c) {
    ull d;
    asm("fma.rn.f32x2 %0, %1, %2, %3;" : "=l"(d) : "l"(a), "l"(b), "l"(c));
    return d;
}
static __device__ __forceinline__ float fin(ull v) {
    float2 f = *(float2*)&v;
    return f.x + f.y;
}
static __device__ __forceinline__ ull packkey(float s, int j) {
    unsigned u = __float_as_uint(s);
    u = (u & 0x80000000u) ? ~u : (u | 0x80000000u);
    return ((ull)u << 32) | (ull)(0xFFFFFFFFu - (unsigned)j);
}
static __device__ __forceinline__ void cpa16(unsigned dst, const float* src) {
    asm volatile("cp.async.cg.shared.global [%0],[%1],16;" :: "r"(dst), "l"(src));
}

// two-level grid barrier: 8-block groups -> global counter -> sense (validated R11)
static __device__ __forceinline__ void gridbar(unsigned& phase) {
    __syncthreads();
    if (threadIdx.x == 0) {
        phase += 1;
        const unsigned grid = gridDim.x;
        const unsigned g = blockIdx.x >> 3;
        const unsigned ngroups = (grid + 7u) >> 3;
        unsigned gsz = grid - (g << 3); if (gsz > 8u) gsz = 8u;
        unsigned old;
        asm volatile("atom.acq_rel.gpu.global.add.u32 %0,[%1],%2;"
                     : "=r"(old) : "l"(&g_gcnt[g]), "r"(1u) : "memory");
        if (old == gsz - 1u) {
            g_gcnt[g] = 0u;
            unsigned old2;
            asm volatile("atom.acq_rel.gpu.global.add.u32 %0,[%1],%2;"
                         : "=r"(old2) : "l"(&g_barcnt), "r"(1u) : "memory");
            if (old2 == ngroups - 1u) {
                g_barcnt = 0u;
                asm volatile("st.release.gpu.global.u32 [%0],%1;"
                             :: "l"(&g_barsense), "r"(phase) : "memory");
            }
        }
        unsigned v;
        do {
            asm volatile("ld.acquire.gpu.global.u32 %0,[%1];"
                         : "=r"(v) : "l"(&g_barsense) : "memory");
            if (v == phase) break;
            __nanosleep(32);
        } while (1);
    }
    __syncthreads();
}
static __device__ __forceinline__ int grab(unsigned base, int tid, int* su) {
    __syncthreads();
    if (tid == 0) *su = (int)(atomicAdd(&g_tick, 1u) - base);
    __syncthreads();
    return *su;
}

// smem: X buffers at 0/4352 (64 rows * 68); W buffers at 8704/12800
#define LDX(buf, kk) do { _Pragma("unroll") for (int i_=0;i_<4;++i_){                  \
    int idx=tid+i_*256; int r=idx>>4, q=idx&15;                                        \
    cpa16(sb+((buf)*4352+r*68+4*q)*4, Xb+(size_t)r*xs+(kk)+4*q); } } while(0)
#define LDXP(buf, kk) do { _Pragma("unroll") for (int i_=0;i_<4;++i_){                 \
    int idx=tid+i_*256; int r=idx>>4, q=idx&15;                                        \
    cpa16(sb+((buf)*4352+r*68+4*q)*4, prow[r]+(kk)+4*q); } } while(0)
#define LDW64(buf, kk) do { _Pragma("unroll") for (int i_=0;i_<4;++i_){                \
    int idx=tid+i_*256; int r=idx>>4, q=idx&15; int row=j0+r; if(row>maxr)row=maxr;    \
    cpa16(sb+(8704+(buf)*4096+(r&1)*2048+(q*32+(r>>1))*4)*4,                           \
          Wb+(size_t)row*ws+(kk)+4*q); } } while(0)
#define LDW32(buf, kk) do { _Pragma("unroll") for (int i_=0;i_<2;++i_){                \
    int idx=tid+i_*256; int r=idx>>4, q=idx&15;                                        \
    cpa16(sb+(8704+(buf)*4096+(q*32+r)*4)*4, Wb+(size_t)r*ws+(kk)+4*q); } } while(0)
#define COMMIT() asm volatile("cp.async.commit_group;")
#define WAIT1()  asm volatile("cp.async.wait_group 1;")
#define WAIT0()  asm volatile("cp.async.wait_group 0;")

static __device__ __forceinline__ void core64(ull acc[8][2], const float* Xs,
                                              const U2* We, const U2* Wo,
                                              int lane, int b0) {
#pragma unroll 4
    for (int q = 0; q < 16; ++q) {
        U2 we = We[q * 32 + lane];
        U2 wo = Wo[q * 32 + lane];
#pragma unroll
        for (int r = 0; r < 8; ++r) {
            U2 xv = *(const U2*)(Xs + (b0 + r) * 68 + 4 * q);
            acc[r][0] = ffma2(xv.lo, we.lo, acc[r][0]);
            acc[r][0] = ffma2(xv.hi, we.hi, acc[r][0]);
            acc[r][1] = ffma2(xv.lo, wo.lo, acc[r][1]);
            acc[r][1] = ffma2(xv.hi, wo.hi, acc[r][1]);
        }
    }
}

// 64-row x 64-col unit, nch K-chunks of 64 starting at k00
static __device__ void gemm64(ull acc[8][2], const float* Xb, size_t xs,
                              const float* const* prow, const float* Wb, size_t ws,
                              int j0, int maxr, int nch, int k00,
                              int tid, unsigned sb, float* S) {
    const int lane = tid & 31, b0 = (tid >> 5) << 3;
#pragma unroll
    for (int r = 0; r < 8; ++r) { acc[r][0] = 0ull; acc[r][1] = 0ull; }
    if (prow) LDXP(0, k00); else LDX(0, k00);
    LDW64(0, k00); COMMIT();
    for (int c = 0; c < nch; ++c) {
        int buf = c & 1;
        if (c + 1 < nch) {
            int k = k00 + (c + 1) * 64;
            if (prow) LDXP(buf ^ 1, k); else LDX(buf ^ 1, k);
            LDW64(buf ^ 1, k); COMMIT(); WAIT1();
        } else WAIT0();
        __syncthreads();
        const U2* We = (const U2*)(S + 8704 + buf * 4096);
        core64(acc, S + buf * 4352, We, We + 512, lane, b0);
        __syncthreads();
    }
}

extern __shared__ float S[];

__global__ __launch_bounds__(TPB, 2)
void mega(const float* __restrict__ feat, const float* __restrict__ A,
          const float* __restrict__ protos, const float* __restrict__ semb,
          const float* __restrict__ sta, const float* __restrict__ unkv,
          const float* __restrict__ Wih, const float* __restrict__ Whh,
          const float* __restrict__ bih, const float* __restrict__ bhh,
          const float* __restrict__ alphap, const float* __restrict__ biasp,
          const float* __restrict__ unkscrp, float* __restrict__ out) {
    __shared__ const float* prow[64];
    __shared__ int su;
    const int tid = threadIdx.x, bid = blockIdx.x;
    const int gid = bid * TPB + tid, gth = gridDim.x * TPB;
    const int lane = tid & 31, b0 = (tid >> 5) << 3;
    unsigned sb = (unsigned)__cvta_generic_to_shared(S);
    unsigned phase = *(volatile unsigned*)&g_barsense;
    unsigned base = 0;
    const float alpha = *alphap, bias = *biasp, unkscr = *unkscrp;

    // -------- P0a: init + out_attns + einsum --------
    for (int i = gid; i < NB * NC; i += gth) g_h[i] = 0.f;
    if (gid < NB) g_amax[1][gid] = (ull)(0xFFFFFFFFu - 4001u);  // sentinel -> STA row
    {
        const float4* A4 = (const float4*)A;
        float4* O4 = (float4*)(out + (size_t)NB * NT * NCLASS);
        for (int i = gid; i < NB * NT * NHW / 4; i += gth) O4[i] = A4[i];
    }
    for (;;) {  // einsum: 512 units, 64 c-rows x 32 t-cols, K=768
        int u = grab(base, tid, &su);
        if (u >= 512) break;
        const int b = u & 63, c0 = (u >> 6) << 6;
        const float* Xb = feat + ((size_t)b * NC + c0) * NHW; size_t xs = NHW;
        const float* Wb = A + (size_t)b * NT * NHW; size_t ws = NHW;
        ull acc[8];
#pragma unroll
        for (int r = 0; r < 8; ++r) acc[r] = 0ull;
        LDX(0, 0); LDW32(0, 0); COMMIT();
        for (int c = 0; c < 12; ++c) {
            int buf = c & 1;
            if (c < 11) { LDX(buf ^ 1, (c + 1) * 64); LDW32(buf ^ 1, (c + 1) * 64); COMMIT(); WAIT1(); }
            else WAIT0();
            __syncthreads();
            const float* Xs = S + buf * 4352;
            const U2* Wq = (const U2*)(S + 8704 + buf * 4096);
#pragma unroll 4
            for (int q = 0; q < 16; ++q) {
                U2 wq = Wq[q * 32 + lane];
#pragma unroll
                for (int r = 0; r < 8; ++r) {
                    U2 xv = *(const U2*)(Xs + (b0 + r) * 68 + 4 * q);
                    acc[r] = ffma2(xv.lo, wq.lo, acc[r]);
                    acc[r] = ffma2(xv.hi, wq.hi, acc[r]);
                }
            }
            __syncthreads();
        }
#pragma unroll
        for (int r = 0; r < 8; ++r)
            g_C[(size_t)lane * NB * NC + (size_t)b * NC + c0 + b0 + r] = fin(acc[r]);
    }
    base += 512 + gridDim.x;
    gridbar(phase);

    // -------- P0b: giC (768 units) + T table (1512 units) --------
    for (;;) {
        int u = grab(base, tid, &su);
        if (u >= 2280) break;
        ull acc[8][2];
        if (u < 768) {
            const int m0 = (u & 31) << 6, j0 = (u >> 5) << 6;
            gemm64(acc, g_C + (size_t)m0 * NC, NC, 0, Wih, 1024, j0, NG - 1, 8, 0, tid, sb, S);
#pragma unroll
            for (int r = 0; r < 8; ++r)
                *(float2*)&g_giC[(size_t)(m0 + b0 + r) * NG + j0 + 2 * lane] =
                    make_float2(fin(acc[r][0]), fin(acc[r][1]));
        } else {
            const int u3 = u - 768;
            const int r0 = (u3 % 63) << 6, j0 = (u3 / 63) << 6;
            if (tid < 64) {
                int i = r0 + tid; if (i > NPROTO + 1) i = NPROTO + 1;
                prow[tid] = (i < NPROTO) ? semb + (size_t)i * NC : ((i == NPROTO) ? unkv : sta);
            }
            __syncthreads();
            gemm64(acc, 0, 0, prow, Wih + 512, 1024, j0, NG - 1, 8, 0, tid, sb, S);
#pragma unroll
            for (int r = 0; r < 8; ++r)
                *(float2*)&g_T[(size_t)(r0 + b0 + r) * NG + j0 + 2 * lane] =
                    make_float2(fin(acc[r][0]), fin(acc[r][1]));
        }
    }
    base += 2280 + gridDim.x;
    gridbar(phase);

    // -------- time loop: t = 0..NT (A: GEMMs, B: reduce+argmax, C: GRU) --------
    for (int t = 0; t <= NT; ++t) {
        const int rawC = (t >= 1) ? 63 * NSL : 0;   // 64j x 128k slices
        const int ghC = (t < NT) ? 24 * NSL : 0;
        if (t >= 1 && bid == 0 && tid < NB) g_amax[(t - 1) & 1][tid] = 0ull;
        for (;;) {
            int u = grab(base, tid, &su);
            if (u >= rawC + ghC) break;
            ull acc[8][2];
            if (u < rawC) {
                const int ju = u % 63, sl = u / 63, j0 = ju << 6, k0 = sl << 7;
                gemm64(acc, g_h, NC, 0, protos, NC, j0, NPROTO - 1, 2, k0, tid, sb, S);
                float* P = g_Praw + (size_t)sl * NB * 4032;
#pragma unroll
                for (int r = 0; r < 8; ++r)
                    *(float2*)&P[(b0 + r) * 4032 + j0 + 2 * lane] =
                        make_float2(fin(acc[r][0]), fin(acc[r][1]));
            } else {
                const int u2 = u - rawC;
                const int ju = u2 % 24, sl = u2 / 24, j0 = ju << 6, k0 = sl << 7;
                gemm64(acc, g_h, NC, 0, Whh, NC, j0, NG - 1, 2, k0, tid, sb, S);
                float* P = g_Pgh + (size_t)sl * NB * NG;
#pragma unroll
                for (int r = 0; r < 8; ++r)
                    *(float2*)&P[(b0 + r) * NG + j0 + 2 * lane] =
                        make_float2(fin(acc[r][0]), fin(acc[r][1]));
            }
        }
        base += rawC + ghC + gridDim.x;
        gridbar(phase);

        if (t >= 1) {  // B: reduce raw(t-1), write scores, argmax
            const int tp = t - 1;
            for (int f = gid; f < NB * 4096; f += gth) {
                const int b = f >> 12, j = f & 4095;
                ull key = 0ull;
                if (j < NPROTO) {
                    float s = 0.f;
#pragma unroll
                    for (int sl = 0; sl < NSL; ++sl)
                        s += g_Praw[(size_t)sl * NB * 4032 + b * 4032 + j];
                    float sc = s * alpha + bias;
                    out[((size_t)b * NT + tp) * NCLASS + j] = sc;
                    key = packkey(sc, j);
                }
#pragma unroll
                for (int off = 16; off >= 1; off >>= 1) {
                    ull o = __shfl_xor_sync(0xFFFFFFFFu, key, off);
                    if (o > key) key = o;
                }
                if (lane == 0) atomicMax(&g_amax[tp & 1][b], key);
            }
            if (bid == 0 && tid < NB) {
                out[((size_t)tid * NT + tp) * NCLASS + NPROTO] = unkscr;
                atomicMax(&g_amax[tp & 1][tid], packkey(unkscr, NPROTO));
            }
        }
        gridbar(phase);

        if (t < NT && gid < NB * NC) {  // C: GRU pointwise
            const int b = gid >> 9, c = gid & 511;
            unsigned idx = 0xFFFFFFFFu - (unsigned)(g_amax[(t + 1) & 1][b] & 0xFFFFFFFFull);
            const float* Tr = g_T + (size_t)idx * NG;
            const float* Gi = g_giC + ((size_t)t * NB + b) * NG;
            float hr = 0.f, hz = 0.f, hn = 0.f;
#pragma unroll
            for (int sl = 0; sl < NSL; ++sl) {
                const float* P = g_Pgh + (size_t)sl * NB * NG + b * NG;
                hr += P[c]; hz += P[512 + c]; hn += P[1024 + c];
            }
            float ir = Gi[c] + Tr[c] + bih[c];
            float iz = Gi[512 + c] + Tr[512 + c] + bih[512 + c];
            float inn = Gi[1024 + c] + Tr[1024 + c] + bih[1024 + c];
            hr += bhh[c]; hz += bhh[512 + c]; hn += bhh[1024 + c];
            double r = 1.0 / (1.0 + exp(-(double)(ir + hr)));
            double z = 1.0 / (1.0 + exp(-(double)(iz + hz)));
            double n = tanh((double)inn + r * (double)hn);
            float hold = g_h[gid];
            g_h[gid] = (float)((1.0 - z) * n + z * (double)hold);
        }
        gridbar(phase);
    }
    if (bid == 0 && tid == 0) g_tick = 0u;  // reset for next graph replay
}

extern "C" void kernel_launch(void* const* d_in, const int* in_sizes, int n_in,
                              void* d_out, int out_size) {
    const float* feature = (const float*)d_in[0];
    const float* A       = (const float*)d_in[1];
    const float* protos  = (const float*)d_in[2];
    const float* semb    = (const float*)d_in[3];
    const float* sta     = (const float*)d_in[4];
    const float* unkv    = (const float*)d_in[5];
    const float* Wih     = (const float*)d_in[6];
    const float* Whh     = (const float*)d_in[7];
    const float* bih     = (const float*)d_in[8];
    const float* bhh     = (const float*)d_in[9];
    const float* alphap  = (const float*)d_in[10];
    const float* biasp   = (const float*)d_in[11];
    const float* unkscrp = (const float*)d_in[12];
    float* out = (float*)d_out;

    int dev = 0; cudaGetDevice(&dev);
    int sms = 148;
    cudaDeviceGetAttribute(&sms, cudaDevAttrMultiProcessorCount, dev);
    cudaFuncSetAttribute(mega, cudaFuncAttributeMaxDynamicSharedMemorySize, SMEM_BYTES);
    mega<<<2 * sms, TPB, SMEM_BYTES>>>(feature, A, protos, semb, sta, unkv,
                                       Wih, Whh, bih, bhh, alphap, biasp, unkscrp, out);
}